// round 2
// baseline (speedup 1.0000x reference)
#include <cuda_runtime.h>

#define N_ENT  100000
#define N_EDGE 500000
#define N_SEED 10000
#define DIM    128
#define E2     (2 * N_EDGE)

// ---------------- scratch (static device globals; no runtime allocation) ----
__device__ __align__(16) int   g_deg[N_ENT];
__device__ __align__(16) int   g_off[N_ENT + 1];
__device__ __align__(16) int   g_cur[N_ENT];
__device__ __align__(16) float g_inv[N_ENT];
__device__ __align__(16) float g_selfw[N_ENT];
__device__ __align__(16) int   g_nbr[E2];
__device__ __align__(16) float g_cw[E2];
__device__ __align__(16) float g_z[N_ENT * DIM];
__device__ __align__(16) float g_x1[N_ENT * DIM];
__device__ __align__(16) int   g_bsum[256];
__device__ __align__(16) int   g_bpref[256];

// ---------------- CSR build ------------------------------------------------
__global__ void k_zero_deg() {
    int i = blockIdx.x * 256 + threadIdx.x;
    if (i < N_ENT) g_deg[i] = 0;
}

__global__ void k_count(const int* __restrict__ edges) {
    int i = blockIdx.x * 256 + threadIdx.x;
    if (i < N_EDGE) {
        atomicAdd(&g_deg[edges[2 * i]], 1);
        atomicAdd(&g_deg[edges[2 * i + 1]], 1);
    }
}

// per-block inclusive scan of deg -> g_off[i+1]; block totals -> g_bsum
__global__ void k_scan_a() {
    __shared__ int s[512];
    int b = blockIdx.x, tid = threadIdx.x;
    int i = b * 512 + tid;
    int v = (i < N_ENT) ? g_deg[i] : 0;
    s[tid] = v;
    __syncthreads();
    #pragma unroll
    for (int d = 1; d < 512; d <<= 1) {
        int t = (tid >= d) ? s[tid - d] : 0;
        __syncthreads();
        s[tid] += t;
        __syncthreads();
    }
    if (i < N_ENT) g_off[i + 1] = s[tid];
    if (tid == 511) g_bsum[b] = s[511];
}

// exclusive scan of block sums (nb <= 256)
__global__ void k_scan_b(int nb) {
    __shared__ int s[256];
    int tid = threadIdx.x;
    int v = (tid < nb) ? g_bsum[tid] : 0;
    s[tid] = v;
    __syncthreads();
    #pragma unroll
    for (int d = 1; d < 256; d <<= 1) {
        int t = (tid >= d) ? s[tid - d] : 0;
        __syncthreads();
        s[tid] += t;
        __syncthreads();
    }
    if (tid < nb) g_bpref[tid] = s[tid] - v;
}

// finalize offsets, init cursors, compute normalization terms
__global__ void k_scan_c() {
    int i = blockIdx.x * 256 + threadIdx.x;
    if (i < N_ENT) {
        int inc = g_off[i + 1] + g_bpref[i / 512];
        g_off[i + 1] = inc;
        g_cur[i] = inc - g_deg[i];
        float d = (float)(g_deg[i] + 1);   // +1 self loop
        g_inv[i] = rsqrtf(d);
        g_selfw[i] = 1.0f / d;
    }
    if (i == 0) g_off[0] = 0;
}

__global__ void k_fill(const int* __restrict__ edges) {
    int i = blockIdx.x * 256 + threadIdx.x;
    if (i < N_EDGE) {
        int a = edges[2 * i];
        int b = edges[2 * i + 1];
        float w = g_inv[a] * g_inv[b];
        int p = atomicAdd(&g_cur[a], 1);
        g_nbr[p] = b; g_cw[p] = w;
        p = atomicAdd(&g_cur[b], 1);
        g_nbr[p] = a; g_cw[p] = w;
    }
}

// ---------------- GEMM: Z = X @ W  (M=100000, N=K=128) ---------------------
// block: 256 threads, 64 rows, 64 of 128 cols (blockIdx.y selects half).
// thread t: row = bx*64 + t/4, owns cols {(t&3)*4 + j*16 + q}, j<4, q<4.
__global__ void k_gemm(const float* __restrict__ X,
                       const float* __restrict__ W,
                       float* __restrict__ Z) {
    __shared__ float Ws[128 * 64];
    int by = blockIdx.y;
    int t = threadIdx.x;
    for (int idx = t; idx < 128 * 64; idx += 256) {
        int k = idx >> 6, c = idx & 63;
        Ws[idx] = W[k * DIM + by * 64 + c];
    }
    __syncthreads();

    int row = blockIdx.x * 64 + (t >> 2);
    int cq = t & 3;   // float4 slot within group of 16 cols
    float acc[16];
    #pragma unroll
    for (int j = 0; j < 16; j++) acc[j] = 0.0f;

    if (row < N_ENT) {
        const float* xr = X + row * DIM;
        #pragma unroll 4
        for (int k = 0; k < 128; k++) {
            float a = xr[k];
            const float4* wr = (const float4*)(Ws + k * 64);
            #pragma unroll
            for (int j = 0; j < 4; j++) {
                float4 w = wr[cq + j * 4];
                acc[j * 4 + 0] = fmaf(a, w.x, acc[j * 4 + 0]);
                acc[j * 4 + 1] = fmaf(a, w.y, acc[j * 4 + 1]);
                acc[j * 4 + 2] = fmaf(a, w.z, acc[j * 4 + 2]);
                acc[j * 4 + 3] = fmaf(a, w.w, acc[j * 4 + 3]);
            }
        }
        float4* zr = (float4*)(Z + row * DIM + by * 64);
        #pragma unroll
        for (int j = 0; j < 4; j++)
            zr[cq + j * 4] = make_float4(acc[j * 4 + 0], acc[j * 4 + 1],
                                         acc[j * 4 + 2], acc[j * 4 + 3]);
    }
}

// ---------------- aggregation: Xout[v] = relu(selfw*Z[v] + sum cw*Z[u] + Xin[v])
// one warp per node; lane l owns float4 of dims [4l, 4l+4)
__global__ void k_agg(const float* __restrict__ Z,
                      const float* __restrict__ Xin,
                      float* __restrict__ Xout) {
    int warp = threadIdx.x >> 5;
    int lane = threadIdx.x & 31;
    int v = blockIdx.x * 8 + warp;
    if (v >= N_ENT) return;

    const float4* z4 = (const float4*)Z;
    float sw = g_selfw[v];
    float4 zv = z4[v * 32 + lane];
    float4 acc = make_float4(zv.x * sw, zv.y * sw, zv.z * sw, zv.w * sw);

    int s = g_off[v], e = g_off[v + 1];
    int i = s;
    // unrolled-by-2 for MLP
    for (; i + 1 < e; i += 2) {
        int u0 = g_nbr[i];     float w0 = g_cw[i];
        int u1 = g_nbr[i + 1]; float w1 = g_cw[i + 1];
        float4 a0 = z4[u0 * 32 + lane];
        float4 a1 = z4[u1 * 32 + lane];
        acc.x = fmaf(a0.x, w0, acc.x); acc.y = fmaf(a0.y, w0, acc.y);
        acc.z = fmaf(a0.z, w0, acc.z); acc.w = fmaf(a0.w, w0, acc.w);
        acc.x = fmaf(a1.x, w1, acc.x); acc.y = fmaf(a1.y, w1, acc.y);
        acc.z = fmaf(a1.z, w1, acc.z); acc.w = fmaf(a1.w, w1, acc.w);
    }
    if (i < e) {
        int u = g_nbr[i]; float w = g_cw[i];
        float4 a0 = z4[u * 32 + lane];
        acc.x = fmaf(a0.x, w, acc.x); acc.y = fmaf(a0.y, w, acc.y);
        acc.z = fmaf(a0.z, w, acc.z); acc.w = fmaf(a0.w, w, acc.w);
    }

    float4 xi = ((const float4*)Xin)[v * 32 + lane];
    float4 r;
    r.x = fmaxf(acc.x + xi.x, 0.0f);
    r.y = fmaxf(acc.y + xi.y, 0.0f);
    r.z = fmaxf(acc.z + xi.z, 0.0f);
    r.w = fmaxf(acc.w + xi.w, 0.0f);
    ((float4*)Xout)[v * 32 + lane] = r;
}

// ---------------- seed gather ----------------------------------------------
__global__ void k_gather(const int* __restrict__ seeds,
                         const float* __restrict__ ent,
                         float* __restrict__ out) {
    int i = blockIdx.x * 256 + threadIdx.x;
    if (i < N_SEED * DIM)
        out[i] = ent[seeds[i >> 7] * DIM + (i & 127)];
}

// ---------------- driver ----------------------------------------------------
static void run_graph(const int* edges, const float* emb,
                      const float* W1, const float* W2,
                      const int* seeds, float* o_ent, float* o_seed,
                      float* z, float* x1) {
    const int GB_ENT = (N_ENT + 255) / 256;     // 391
    const int GB_EDGE = (N_EDGE + 255) / 256;   // 1954
    const int NB_SCAN = (N_ENT + 511) / 512;    // 196

    k_zero_deg<<<GB_ENT, 256>>>();
    k_count<<<GB_EDGE, 256>>>(edges);
    k_scan_a<<<NB_SCAN, 512>>>();
    k_scan_b<<<1, 256>>>(NB_SCAN);
    k_scan_c<<<GB_ENT, 256>>>();
    k_fill<<<GB_EDGE, 256>>>(edges);

    dim3 ggrid((N_ENT + 63) / 64, 2);
    // layer 1: z = emb @ W1 ; x1 = relu(A z + emb)
    k_gemm<<<ggrid, 256>>>(emb, W1, z);
    k_agg<<<(N_ENT + 7) / 8, 256>>>(z, emb, x1);
    // layer 2: z = x1 @ W2 ; ent = relu(A z + x1)
    k_gemm<<<ggrid, 256>>>(x1, W2, z);
    k_agg<<<(N_ENT + 7) / 8, 256>>>(z, x1, o_ent);

    k_gather<<<(N_SEED * DIM + 255) / 256, 256>>>(seeds, o_ent, o_seed);
}

extern "C" void kernel_launch(void* const* d_in, const int* in_sizes, int n_in,
                              void* d_out, int out_size) {
    const int*   sr_seeds = (const int*)d_in[0];
    const int*   tg_seeds = (const int*)d_in[1];
    // d_in[2], d_in[3] = triples (unused by reference)
    const float* emb_sr   = (const float*)d_in[4];
    const float* emb_tg   = (const float*)d_in[5];
    const int*   edges_sr = (const int*)d_in[6];
    const int*   edges_tg = (const int*)d_in[7];
    const float* W1       = (const float*)d_in[8];
    const float* W2       = (const float*)d_in[9];

    float* out = (float*)d_out;
    float* o_sr_seed = out;
    float* o_tg_seed = out + (size_t)N_SEED * DIM;
    float* o_sr_ent  = out + (size_t)2 * N_SEED * DIM;
    float* o_tg_ent  = o_sr_ent + (size_t)N_ENT * DIM;

    float* z;  cudaGetSymbolAddress((void**)&z, g_z);
    float* x1; cudaGetSymbolAddress((void**)&x1, g_x1);

    run_graph(edges_sr, emb_sr, W1, W2, sr_seeds, o_sr_ent, o_sr_seed, z, x1);
    run_graph(edges_tg, emb_tg, W1, W2, tg_seeds, o_tg_ent, o_tg_seed, z, x1);
}

// round 4
// speedup vs baseline: 1.2402x; 1.2402x over previous
#include <cuda_runtime.h>

#define N_ENT  100000
#define N_EDGE 500000
#define N_SEED 10000
#define DIM    128
#define E2     (2 * N_EDGE)

typedef unsigned long long ull;

// ---------------- scratch: one set per graph (2 streams run concurrently) ---
__device__ __align__(16) int   g_deg[2][N_ENT];
__device__ __align__(16) int   g_off[2][N_ENT + 1];
__device__ __align__(16) int   g_cur[2][N_ENT];
__device__ __align__(16) float g_inv[2][N_ENT];
__device__ __align__(16) float g_selfw[2][N_ENT];
__device__ __align__(16) int   g_nbr[2][E2];
__device__ __align__(16) float g_cw[2][E2];
__device__ __align__(16) float g_z[2][N_ENT * DIM];
__device__ __align__(16) float g_x1[2][N_ENT * DIM];
__device__ __align__(16) int   g_bsum[2][256];
__device__ __align__(16) int   g_bpref[2][256];

// ---------------- f32x2 packed-FMA helpers (sm_10x) -------------------------
__device__ __forceinline__ ull pack2(float a, float b) {
    ull r;
    asm("mov.b64 %0, {%1, %2};" : "=l"(r) : "f"(a), "f"(b));
    return r;
}
__device__ __forceinline__ ull fma2(ull a, ull b, ull c) {
    ull d;
    asm("fma.rn.f32x2 %0, %1, %2, %3;" : "=l"(d) : "l"(a), "l"(b), "l"(c));
    return d;
}

// ---------------- CSR build ------------------------------------------------
__global__ void k_zero_deg(int g) {
    int i = blockIdx.x * 256 + threadIdx.x;
    if (i < N_ENT) g_deg[g][i] = 0;
}

__global__ void k_count(const int* __restrict__ edges, int g) {
    int i = blockIdx.x * 256 + threadIdx.x;
    if (i < N_EDGE) {
        int2 e = ((const int2*)edges)[i];
        atomicAdd(&g_deg[g][e.x], 1);
        atomicAdd(&g_deg[g][e.y], 1);
    }
}

// per-block inclusive scan of deg -> g_off[i+1]; block totals -> g_bsum
__global__ void k_scan_a(int g) {
    __shared__ int s[512];
    int b = blockIdx.x, tid = threadIdx.x;
    int i = b * 512 + tid;
    int v = (i < N_ENT) ? g_deg[g][i] : 0;
    s[tid] = v;
    __syncthreads();
    #pragma unroll
    for (int d = 1; d < 512; d <<= 1) {
        int t = (tid >= d) ? s[tid - d] : 0;
        __syncthreads();
        s[tid] += t;
        __syncthreads();
    }
    if (i < N_ENT) g_off[g][i + 1] = s[tid];
    if (tid == 511) g_bsum[g][b] = s[511];
}

__global__ void k_scan_b(int nb, int g) {
    __shared__ int s[256];
    int tid = threadIdx.x;
    int v = (tid < nb) ? g_bsum[g][tid] : 0;
    s[tid] = v;
    __syncthreads();
    #pragma unroll
    for (int d = 1; d < 256; d <<= 1) {
        int t = (tid >= d) ? s[tid - d] : 0;
        __syncthreads();
        s[tid] += t;
        __syncthreads();
    }
    if (tid < nb) g_bpref[g][tid] = s[tid] - v;
}

__global__ void k_scan_c(int g) {
    int i = blockIdx.x * 256 + threadIdx.x;
    if (i < N_ENT) {
        int inc = g_off[g][i + 1] + g_bpref[g][i / 512];
        g_off[g][i + 1] = inc;
        g_cur[g][i] = inc - g_deg[g][i];
        float d = (float)(g_deg[g][i] + 1);   // +1 self loop
        g_inv[g][i] = rsqrtf(d);
        g_selfw[g][i] = 1.0f / d;
    }
    if (i == 0) g_off[g][0] = 0;
}

__global__ void k_fill(const int* __restrict__ edges, int g) {
    int i = blockIdx.x * 256 + threadIdx.x;
    if (i < N_EDGE) {
        int2 e = ((const int2*)edges)[i];
        float w = g_inv[g][e.x] * g_inv[g][e.y];
        int p = atomicAdd(&g_cur[g][e.x], 1);
        g_nbr[g][p] = e.y; g_cw[g][p] = w;
        p = atomicAdd(&g_cur[g][e.y], 1);
        g_nbr[g][p] = e.x; g_cw[g][p] = w;
    }
}

// ---------------- GEMM: Z = X @ W  (M=100000, N=K=128), packed f32x2 -------
// block: 256 threads, 64 rows; blockIdx.y picks a 64-col half.
// thread t: row = bx*64 + t/4, cq = t&3 owns float4 cols {cq+4j}, j<4.
__global__ void k_gemm(const float* __restrict__ X,
                       const float* __restrict__ W,
                       float* __restrict__ Z) {
    __shared__ __align__(16) float Ws[128 * 64];
    int by = blockIdx.y;
    int t = threadIdx.x;
    for (int idx = t; idx < 128 * 64; idx += 256) {
        int k = idx >> 6, c = idx & 63;
        Ws[idx] = W[k * DIM + by * 64 + c];
    }
    __syncthreads();

    int row = blockIdx.x * 64 + (t >> 2);
    int cq = t & 3;
    ull acc[8];
    #pragma unroll
    for (int j = 0; j < 8; j++) acc[j] = 0ull;   // packed {0.f, 0.f}

    if (row < N_ENT) {
        const float4* x4 = (const float4*)(X + (size_t)row * DIM);
        #pragma unroll 4
        for (int kk = 0; kk < 32; kk++) {
            float4 xv = __ldg(&x4[kk]);
            #pragma unroll
            for (int q = 0; q < 4; q++) {
                float a = (q == 0) ? xv.x : (q == 1) ? xv.y : (q == 2) ? xv.z : xv.w;
                ull aa = pack2(a, a);
                const ulonglong2* wr =
                    (const ulonglong2*)(Ws + (kk * 4 + q) * 64);
                #pragma unroll
                for (int j = 0; j < 4; j++) {
                    ulonglong2 w = wr[cq + 4 * j];   // LDS.128 -> 2 aligned pairs
                    acc[2 * j]     = fma2(aa, w.x, acc[2 * j]);
                    acc[2 * j + 1] = fma2(aa, w.y, acc[2 * j + 1]);
                }
            }
        }
        ulonglong2* zr = (ulonglong2*)(Z + (size_t)row * DIM + by * 64);
        #pragma unroll
        for (int j = 0; j < 4; j++)
            zr[cq + 4 * j] = make_ulonglong2(acc[2 * j], acc[2 * j + 1]);
    }
}

// ---------------- aggregation: Xout[v] = relu(selfw*Z[v] + sum cw*Z[u] + Xin[v])
// one warp per node; lane l owns float4 of dims [4l, 4l+4)
__global__ void k_agg(const float* __restrict__ Z,
                      const float* __restrict__ Xin,
                      float* __restrict__ Xout, int g) {
    int warp = threadIdx.x >> 5;
    int lane = threadIdx.x & 31;
    int v = blockIdx.x * 8 + warp;
    if (v >= N_ENT) return;

    const float4* z4 = (const float4*)Z;
    float sw = g_selfw[g][v];
    float4 zv = __ldg(&z4[v * 32 + lane]);
    float4 acc = make_float4(zv.x * sw, zv.y * sw, zv.z * sw, zv.w * sw);

    const int* __restrict__ nbr = g_nbr[g];
    const float* __restrict__ cw = g_cw[g];
    int s = g_off[g][v], e = g_off[g][v + 1];
    int i = s;
    for (; i + 3 < e; i += 4) {
        int u0 = nbr[i];     float w0 = cw[i];
        int u1 = nbr[i + 1]; float w1 = cw[i + 1];
        int u2 = nbr[i + 2]; float w2 = cw[i + 2];
        int u3 = nbr[i + 3]; float w3 = cw[i + 3];
        float4 a0 = __ldg(&z4[u0 * 32 + lane]);
        float4 a1 = __ldg(&z4[u1 * 32 + lane]);
        float4 a2 = __ldg(&z4[u2 * 32 + lane]);
        float4 a3 = __ldg(&z4[u3 * 32 + lane]);
        acc.x = fmaf(a0.x, w0, acc.x); acc.y = fmaf(a0.y, w0, acc.y);
        acc.z = fmaf(a0.z, w0, acc.z); acc.w = fmaf(a0.w, w0, acc.w);
        acc.x = fmaf(a1.x, w1, acc.x); acc.y = fmaf(a1.y, w1, acc.y);
        acc.z = fmaf(a1.z, w1, acc.z); acc.w = fmaf(a1.w, w1, acc.w);
        acc.x = fmaf(a2.x, w2, acc.x); acc.y = fmaf(a2.y, w2, acc.y);
        acc.z = fmaf(a2.z, w2, acc.z); acc.w = fmaf(a2.w, w2, acc.w);
        acc.x = fmaf(a3.x, w3, acc.x); acc.y = fmaf(a3.y, w3, acc.y);
        acc.z = fmaf(a3.z, w3, acc.z); acc.w = fmaf(a3.w, w3, acc.w);
    }
    for (; i < e; i++) {
        int u = nbr[i]; float w = cw[i];
        float4 a0 = __ldg(&z4[u * 32 + lane]);
        acc.x = fmaf(a0.x, w, acc.x); acc.y = fmaf(a0.y, w, acc.y);
        acc.z = fmaf(a0.z, w, acc.z); acc.w = fmaf(a0.w, w, acc.w);
    }

    float4 xi = __ldg(&((const float4*)Xin)[v * 32 + lane]);
    float4 r;
    r.x = fmaxf(acc.x + xi.x, 0.0f);
    r.y = fmaxf(acc.y + xi.y, 0.0f);
    r.z = fmaxf(acc.z + xi.z, 0.0f);
    r.w = fmaxf(acc.w + xi.w, 0.0f);
    ((float4*)Xout)[v * 32 + lane] = r;
}

// ---------------- seed gather ----------------------------------------------
__global__ void k_gather(const int* __restrict__ seeds,
                         const float* __restrict__ ent,
                         float* __restrict__ out) {
    int i = blockIdx.x * 256 + threadIdx.x;
    if (i < N_SEED * 32) {
        int s = i >> 5, q = i & 31;
        ((float4*)out)[i] = __ldg(&((const float4*)ent)[seeds[s] * 32 + q]);
    }
}

// ---------------- driver ----------------------------------------------------
static void run_graph(const int* edges, const float* emb,
                      const float* W1, const float* W2,
                      const int* seeds, float* o_ent, float* o_seed,
                      float* z, float* x1, int g, cudaStream_t st) {
    const int GB_ENT = (N_ENT + 255) / 256;     // 391
    const int GB_EDGE = (N_EDGE + 255) / 256;   // 1954
    const int NB_SCAN = (N_ENT + 511) / 512;    // 196

    k_zero_deg<<<GB_ENT, 256, 0, st>>>(g);
    k_count<<<GB_EDGE, 256, 0, st>>>(edges, g);
    k_scan_a<<<NB_SCAN, 512, 0, st>>>(g);
    k_scan_b<<<1, 256, 0, st>>>(NB_SCAN, g);
    k_scan_c<<<GB_ENT, 256, 0, st>>>(g);
    k_fill<<<GB_EDGE, 256, 0, st>>>(edges, g);

    dim3 ggrid((N_ENT + 63) / 64, 2);
    // layer 1: z = emb @ W1 ; x1 = relu(A z + emb)
    k_gemm<<<ggrid, 256, 0, st>>>(emb, W1, z);
    k_agg<<<(N_ENT + 7) / 8, 256, 0, st>>>(z, emb, x1, g);
    // layer 2: z = x1 @ W2 ; ent = relu(A z + x1)
    k_gemm<<<ggrid, 256, 0, st>>>(x1, W2, z);
    k_agg<<<(N_ENT + 7) / 8, 256, 0, st>>>(z, x1, o_ent, g);

    k_gather<<<(N_SEED * 32 + 255) / 256, 256, 0, st>>>(seeds, o_ent, o_seed);
}

extern "C" void kernel_launch(void* const* d_in, const int* in_sizes, int n_in,
                              void* d_out, int out_size) {
    const int*   sr_seeds = (const int*)d_in[0];
    const int*   tg_seeds = (const int*)d_in[1];
    // d_in[2], d_in[3] = triples (unused by reference)
    const float* emb_sr   = (const float*)d_in[4];
    const float* emb_tg   = (const float*)d_in[5];
    const int*   edges_sr = (const int*)d_in[6];
    const int*   edges_tg = (const int*)d_in[7];
    const float* W1       = (const float*)d_in[8];
    const float* W2       = (const float*)d_in[9];

    float* out = (float*)d_out;
    float* o_sr_seed = out;
    float* o_tg_seed = out + (size_t)N_SEED * DIM;
    float* o_sr_ent  = out + (size_t)2 * N_SEED * DIM;
    float* o_tg_ent  = o_sr_ent + (size_t)N_ENT * DIM;

    float* zbase;  cudaGetSymbolAddress((void**)&zbase, g_z);
    float* x1base; cudaGetSymbolAddress((void**)&x1base, g_x1);

    // one extra stream + fork/join events, created once (outside capture)
    static cudaStream_t s_tg = nullptr;
    static cudaEvent_t ev_fork = nullptr, ev_join = nullptr;
    if (!s_tg) {
        cudaStreamCreateWithFlags(&s_tg, cudaStreamNonBlocking);
        cudaEventCreateWithFlags(&ev_fork, cudaEventDisableTiming);
        cudaEventCreateWithFlags(&ev_join, cudaEventDisableTiming);
    }

    // fork: tg pipeline on side stream, sr pipeline on the capture stream
    cudaEventRecord(ev_fork, 0);
    cudaStreamWaitEvent(s_tg, ev_fork, 0);

    run_graph(edges_sr, emb_sr, W1, W2, sr_seeds, o_sr_ent, o_sr_seed,
              zbase, x1base, 0, 0);
    run_graph(edges_tg, emb_tg, W1, W2, tg_seeds, o_tg_ent, o_tg_seed,
              zbase + (size_t)N_ENT * DIM, x1base + (size_t)N_ENT * DIM,
              1, s_tg);

    // join
    cudaEventRecord(ev_join, s_tg);
    cudaStreamWaitEvent(0, ev_join, 0);
}

// round 5
// speedup vs baseline: 1.8996x; 1.5317x over previous
#include <cuda_runtime.h>

#define N_ENT  100000
#define N_EDGE 500000
#define N_SEED 10000
#define DIM    128
#define E2     (2 * N_EDGE)

typedef unsigned long long ull;

// ---------------- scratch: one set per graph (2 streams run concurrently) ---
__device__ __align__(16) int   g_deg[2][N_ENT];
__device__ __align__(16) int   g_off[2][N_ENT + 1];
__device__ __align__(16) int   g_cur[2][N_ENT];
__device__ __align__(16) float g_inv[2][N_ENT];
__device__ __align__(16) float g_selfw[2][N_ENT];
__device__ __align__(16) int   g_nbr[2][E2];
__device__ __align__(16) float g_cw[2][E2];
__device__ __align__(16) float g_z[2][N_ENT * DIM];
__device__ __align__(16) float g_x1[2][N_ENT * DIM];
__device__ __align__(16) int   g_bsum[2][256];
__device__ __align__(16) int   g_bpref[2][256];

// ---------------- f32x2 packed-FMA helpers (sm_10x) -------------------------
__device__ __forceinline__ ull pack2(float a, float b) {
    ull r;
    asm("mov.b64 %0, {%1, %2};" : "=l"(r) : "f"(a), "f"(b));
    return r;
}
__device__ __forceinline__ ull fma2(ull a, ull b, ull c) {
    ull d;
    asm("fma.rn.f32x2 %0, %1, %2, %3;" : "=l"(d) : "l"(a), "l"(b), "l"(c));
    return d;
}
__device__ __forceinline__ void unpack2(ull v, float& lo, float& hi) {
    asm("mov.b64 {%0, %1}, %2;" : "=f"(lo), "=f"(hi) : "l"(v));
}

// ---------------- CSR build ------------------------------------------------
__global__ void k_zero_deg(int g) {
    int i = blockIdx.x * 256 + threadIdx.x;
    if (i < N_ENT) g_deg[g][i] = 0;
}

__global__ void k_count(const int* __restrict__ edges, int g) {
    int i = blockIdx.x * 256 + threadIdx.x;
    if (i < N_EDGE) {
        int2 e = ((const int2*)edges)[i];
        atomicAdd(&g_deg[g][e.x], 1);
        atomicAdd(&g_deg[g][e.y], 1);
    }
}

__global__ void k_scan_a(int g) {
    __shared__ int s[512];
    int b = blockIdx.x, tid = threadIdx.x;
    int i = b * 512 + tid;
    int v = (i < N_ENT) ? g_deg[g][i] : 0;
    s[tid] = v;
    __syncthreads();
    #pragma unroll
    for (int d = 1; d < 512; d <<= 1) {
        int t = (tid >= d) ? s[tid - d] : 0;
        __syncthreads();
        s[tid] += t;
        __syncthreads();
    }
    if (i < N_ENT) g_off[g][i + 1] = s[tid];
    if (tid == 511) g_bsum[g][b] = s[511];
}

__global__ void k_scan_b(int nb, int g) {
    __shared__ int s[256];
    int tid = threadIdx.x;
    int v = (tid < nb) ? g_bsum[g][tid] : 0;
    s[tid] = v;
    __syncthreads();
    #pragma unroll
    for (int d = 1; d < 256; d <<= 1) {
        int t = (tid >= d) ? s[tid - d] : 0;
        __syncthreads();
        s[tid] += t;
        __syncthreads();
    }
    if (tid < nb) g_bpref[g][tid] = s[tid] - v;
}

__global__ void k_scan_c(int g) {
    int i = blockIdx.x * 256 + threadIdx.x;
    if (i < N_ENT) {
        int inc = g_off[g][i + 1] + g_bpref[g][i / 512];
        g_off[g][i + 1] = inc;
        g_cur[g][i] = inc - g_deg[g][i];
        float d = (float)(g_deg[g][i] + 1);   // +1 self loop
        g_inv[g][i] = rsqrtf(d);
        g_selfw[g][i] = 1.0f / d;
    }
    if (i == 0) g_off[g][0] = 0;
}

__global__ void k_fill(const int* __restrict__ edges, int g) {
    int i = blockIdx.x * 256 + threadIdx.x;
    if (i < N_EDGE) {
        int2 e = ((const int2*)edges)[i];
        float w = g_inv[g][e.x] * g_inv[g][e.y];
        int p = atomicAdd(&g_cur[g][e.x], 1);
        g_nbr[g][p] = e.y; g_cw[g][p] = w;
        p = atomicAdd(&g_cur[g][e.y], 1);
        g_nbr[g][p] = e.x; g_cw[g][p] = w;
    }
}

// ---------------- GEMM: Z = X @ W  (M=100000, N=K=128), reg-blocked f32x2 ---
// BM=128, BN=128, BK=16. 128 threads = 8(ty) x 16(tx).
// Thread tile: 16 rows (ty*16..+16) x 8 cols (tx*8..+8) as 8x8 ull accs
// (row-pairs packed). As stored k-major so row pairs load as aligned ull.
#define BK 16

__global__ __launch_bounds__(128, 2)
void k_gemm(const float* __restrict__ X,
            const float* __restrict__ W,
            float* __restrict__ Z) {
    __shared__ __align__(16) float As[2][BK * 128];
    __shared__ __align__(16) float Bs[2][BK * 128];

    const int t  = threadIdx.x;
    const int tx = t & 15;          // col group: cols tx*8..+8
    const int ty = t >> 4;          // row group: rows ty*16..+16
    const int rowBase = blockIdx.x * 128;

    // A-tile load mapping: float4 idx f = t + 128*i (i<4):
    //   arow = f/4 (0..127), ak4 = f%4 (k-quad)
    const int arow = t >> 2;        // + 32*i
    const int ak4  = t & 3;
    // B-tile: f = t + 128*i: bk = f/32, bc4 = f%32
    const int bk0  = t >> 5;        // + 4*i
    const int bc4  = t & 31;

    float4 aReg[4], bReg[4];

    // prologue: fetch chunk 0
    {
        #pragma unroll
        for (int i = 0; i < 4; i++) {
            int gr = rowBase + arow + 32 * i;
            if (gr >= N_ENT) gr = N_ENT - 1;            // clamp (stores guarded)
            aReg[i] = __ldg((const float4*)(X + (size_t)gr * DIM + ak4 * 4));
            bReg[i] = __ldg((const float4*)(W + (size_t)(bk0 + 4 * i) * DIM + bc4 * 4));
        }
        #pragma unroll
        for (int i = 0; i < 4; i++) {
            float* a = As[0] + (ak4 * 4) * 128 + arow + 32 * i;   // As[k][row]
            a[0] = aReg[i].x; a[128] = aReg[i].y;
            a[256] = aReg[i].z; a[384] = aReg[i].w;
            *(float4*)(Bs[0] + (bk0 + 4 * i) * 128 + bc4 * 4) = bReg[i];
        }
    }
    __syncthreads();

    ull acc[8][8];
    #pragma unroll
    for (int r = 0; r < 8; r++)
        #pragma unroll
        for (int c = 0; c < 8; c++) acc[r][c] = 0ull;

    #pragma unroll
    for (int kc = 0; kc < 8; kc++) {
        int buf = kc & 1;
        // prefetch next chunk into registers
        if (kc < 7) {
            int kOff = (kc + 1) * BK;
            #pragma unroll
            for (int i = 0; i < 4; i++) {
                int gr = rowBase + arow + 32 * i;
                if (gr >= N_ENT) gr = N_ENT - 1;
                aReg[i] = __ldg((const float4*)(X + (size_t)gr * DIM + kOff + ak4 * 4));
                bReg[i] = __ldg((const float4*)(W + (size_t)(kOff + bk0 + 4 * i) * DIM + bc4 * 4));
            }
        }
        // compute on current buffer
        #pragma unroll
        for (int k = 0; k < BK; k++) {
            ull ap[8];
            const ulonglong2* arowp =
                (const ulonglong2*)(As[buf] + k * 128 + ty * 16);
            #pragma unroll
            for (int i = 0; i < 4; i++) {
                ulonglong2 v = arowp[i];
                ap[2 * i] = v.x; ap[2 * i + 1] = v.y;
            }
            float4 b0 = *(const float4*)(Bs[buf] + k * 128 + tx * 8);
            float4 b1 = *(const float4*)(Bs[buf] + k * 128 + tx * 8 + 4);
            ull bb[8];
            bb[0] = pack2(b0.x, b0.x); bb[1] = pack2(b0.y, b0.y);
            bb[2] = pack2(b0.z, b0.z); bb[3] = pack2(b0.w, b0.w);
            bb[4] = pack2(b1.x, b1.x); bb[5] = pack2(b1.y, b1.y);
            bb[6] = pack2(b1.z, b1.z); bb[7] = pack2(b1.w, b1.w);
            #pragma unroll
            for (int c = 0; c < 8; c++)
                #pragma unroll
                for (int rp = 0; rp < 8; rp++)
                    acc[rp][c] = fma2(ap[rp], bb[c], acc[rp][c]);
        }
        // stage next chunk into the other buffer
        if (kc < 7) {
            int nb = buf ^ 1;
            #pragma unroll
            for (int i = 0; i < 4; i++) {
                float* a = As[nb] + (ak4 * 4) * 128 + arow + 32 * i;
                a[0] = aReg[i].x; a[128] = aReg[i].y;
                a[256] = aReg[i].z; a[384] = aReg[i].w;
                *(float4*)(Bs[nb] + (bk0 + 4 * i) * 128 + bc4 * 4) = bReg[i];
            }
            __syncthreads();
        }
    }

    // epilogue: unpack row pairs, 2 STG.128 per row
    #pragma unroll
    for (int rp = 0; rp < 8; rp++) {
        int r0 = rowBase + ty * 16 + 2 * rp;
        float lo[8], hi[8];
        #pragma unroll
        for (int c = 0; c < 8; c++) unpack2(acc[rp][c], lo[c], hi[c]);
        if (r0 < N_ENT) {
            float4* zr = (float4*)(Z + (size_t)r0 * DIM + tx * 8);
            zr[0] = make_float4(lo[0], lo[1], lo[2], lo[3]);
            zr[1] = make_float4(lo[4], lo[5], lo[6], lo[7]);
        }
        if (r0 + 1 < N_ENT) {
            float4* zr = (float4*)(Z + (size_t)(r0 + 1) * DIM + tx * 8);
            zr[0] = make_float4(hi[0], hi[1], hi[2], hi[3]);
            zr[1] = make_float4(hi[4], hi[5], hi[6], hi[7]);
        }
    }
}

// ---------------- aggregation: Xout[v] = relu(selfw*Z[v] + sum cw*Z[u] + Xin[v])
__global__ void k_agg(const float* __restrict__ Z,
                      const float* __restrict__ Xin,
                      float* __restrict__ Xout, int g) {
    int warp = threadIdx.x >> 5;
    int lane = threadIdx.x & 31;
    int v = blockIdx.x * 8 + warp;
    if (v >= N_ENT) return;

    const float4* z4 = (const float4*)Z;
    float sw = g_selfw[g][v];
    float4 zv = __ldg(&z4[v * 32 + lane]);
    float4 acc = make_float4(zv.x * sw, zv.y * sw, zv.z * sw, zv.w * sw);

    const int* __restrict__ nbr = g_nbr[g];
    const float* __restrict__ cw = g_cw[g];
    int s = g_off[g][v], e = g_off[g][v + 1];
    int i = s;
    for (; i + 3 < e; i += 4) {
        int u0 = nbr[i];     float w0 = cw[i];
        int u1 = nbr[i + 1]; float w1 = cw[i + 1];
        int u2 = nbr[i + 2]; float w2 = cw[i + 2];
        int u3 = nbr[i + 3]; float w3 = cw[i + 3];
        float4 a0 = __ldg(&z4[u0 * 32 + lane]);
        float4 a1 = __ldg(&z4[u1 * 32 + lane]);
        float4 a2 = __ldg(&z4[u2 * 32 + lane]);
        float4 a3 = __ldg(&z4[u3 * 32 + lane]);
        acc.x = fmaf(a0.x, w0, acc.x); acc.y = fmaf(a0.y, w0, acc.y);
        acc.z = fmaf(a0.z, w0, acc.z); acc.w = fmaf(a0.w, w0, acc.w);
        acc.x = fmaf(a1.x, w1, acc.x); acc.y = fmaf(a1.y, w1, acc.y);
        acc.z = fmaf(a1.z, w1, acc.z); acc.w = fmaf(a1.w, w1, acc.w);
        acc.x = fmaf(a2.x, w2, acc.x); acc.y = fmaf(a2.y, w2, acc.y);
        acc.z = fmaf(a2.z, w2, acc.z); acc.w = fmaf(a2.w, w2, acc.w);
        acc.x = fmaf(a3.x, w3, acc.x); acc.y = fmaf(a3.y, w3, acc.y);
        acc.z = fmaf(a3.z, w3, acc.z); acc.w = fmaf(a3.w, w3, acc.w);
    }
    for (; i < e; i++) {
        int u = nbr[i]; float w = cw[i];
        float4 a0 = __ldg(&z4[u * 32 + lane]);
        acc.x = fmaf(a0.x, w, acc.x); acc.y = fmaf(a0.y, w, acc.y);
        acc.z = fmaf(a0.z, w, acc.z); acc.w = fmaf(a0.w, w, acc.w);
    }

    float4 xi = __ldg(&((const float4*)Xin)[v * 32 + lane]);
    float4 r;
    r.x = fmaxf(acc.x + xi.x, 0.0f);
    r.y = fmaxf(acc.y + xi.y, 0.0f);
    r.z = fmaxf(acc.z + xi.z, 0.0f);
    r.w = fmaxf(acc.w + xi.w, 0.0f);
    ((float4*)Xout)[v * 32 + lane] = r;
}

// ---------------- seed gather ----------------------------------------------
__global__ void k_gather(const int* __restrict__ seeds,
                         const float* __restrict__ ent,
                         float* __restrict__ out) {
    int i = blockIdx.x * 256 + threadIdx.x;
    if (i < N_SEED * 32) {
        int s = i >> 5, q = i & 31;
        ((float4*)out)[i] = __ldg(&((const float4*)ent)[seeds[s] * 32 + q]);
    }
}

// ---------------- driver ----------------------------------------------------
static void run_graph(const int* edges, const float* emb,
                      const float* W1, const float* W2,
                      const int* seeds, float* o_ent, float* o_seed,
                      float* z, float* x1, int g, cudaStream_t st) {
    const int GB_ENT = (N_ENT + 255) / 256;     // 391
    const int GB_EDGE = (N_EDGE + 255) / 256;   // 1954
    const int NB_SCAN = (N_ENT + 511) / 512;    // 196

    k_zero_deg<<<GB_ENT, 256, 0, st>>>(g);
    k_count<<<GB_EDGE, 256, 0, st>>>(edges, g);
    k_scan_a<<<NB_SCAN, 512, 0, st>>>(g);
    k_scan_b<<<1, 256, 0, st>>>(NB_SCAN, g);
    k_scan_c<<<GB_ENT, 256, 0, st>>>(g);
    k_fill<<<GB_EDGE, 256, 0, st>>>(edges, g);

    const int GEMM_GRID = (N_ENT + 127) / 128;  // 782
    // layer 1: z = emb @ W1 ; x1 = relu(A z + emb)
    k_gemm<<<GEMM_GRID, 128, 0, st>>>(emb, W1, z);
    k_agg<<<(N_ENT + 7) / 8, 256, 0, st>>>(z, emb, x1, g);
    // layer 2: z = x1 @ W2 ; ent = relu(A z + x1)
    k_gemm<<<GEMM_GRID, 128, 0, st>>>(x1, W2, z);
    k_agg<<<(N_ENT + 7) / 8, 256, 0, st>>>(z, x1, o_ent, g);

    k_gather<<<(N_SEED * 32 + 255) / 256, 256, 0, st>>>(seeds, o_ent, o_seed);
}

extern "C" void kernel_launch(void* const* d_in, const int* in_sizes, int n_in,
                              void* d_out, int out_size) {
    const int*   sr_seeds = (const int*)d_in[0];
    const int*   tg_seeds = (const int*)d_in[1];
    // d_in[2], d_in[3] = triples (unused by reference)
    const float* emb_sr   = (const float*)d_in[4];
    const float* emb_tg   = (const float*)d_in[5];
    const int*   edges_sr = (const int*)d_in[6];
    const int*   edges_tg = (const int*)d_in[7];
    const float* W1       = (const float*)d_in[8];
    const float* W2       = (const float*)d_in[9];

    float* out = (float*)d_out;
    float* o_sr_seed = out;
    float* o_tg_seed = out + (size_t)N_SEED * DIM;
    float* o_sr_ent  = out + (size_t)2 * N_SEED * DIM;
    float* o_tg_ent  = o_sr_ent + (size_t)N_ENT * DIM;

    float* zbase;  cudaGetSymbolAddress((void**)&zbase, g_z);
    float* x1base; cudaGetSymbolAddress((void**)&x1base, g_x1);

    // one extra stream + fork/join events, created once (outside capture)
    static cudaStream_t s_tg = nullptr;
    static cudaEvent_t ev_fork = nullptr, ev_join = nullptr;
    if (!s_tg) {
        cudaStreamCreateWithFlags(&s_tg, cudaStreamNonBlocking);
        cudaEventCreateWithFlags(&ev_fork, cudaEventDisableTiming);
        cudaEventCreateWithFlags(&ev_join, cudaEventDisableTiming);
    }

    // fork: tg pipeline on side stream, sr pipeline on the capture stream
    cudaEventRecord(ev_fork, 0);
    cudaStreamWaitEvent(s_tg, ev_fork, 0);

    run_graph(edges_sr, emb_sr, W1, W2, sr_seeds, o_sr_ent, o_sr_seed,
              zbase, x1base, 0, 0);
    run_graph(edges_tg, emb_tg, W1, W2, tg_seeds, o_tg_ent, o_tg_seed,
              zbase + (size_t)N_ENT * DIM, x1base + (size_t)N_ENT * DIM,
              1, s_tg);

    // join
    cudaEventRecord(ev_join, s_tg);
    cudaStreamWaitEvent(0, ev_join, 0);
}